// round 14
// baseline (speedup 1.0000x reference)
#include <cuda_runtime.h>
#include <cuda_fp16.h>
#include <cuda_bf16.h>
#include <cstdint>

#define N_NODES_MAX 100000
#define E_MAX       1600000
#define F           128
#define SCHUNK      100      // elements per scan thread (1024 threads, 1 block)

// ===========================================================================
// Scratch (allocation-free contract: __device__ globals)
// ===========================================================================
__device__ __half g_feat_h[(long)N_NODES_MAX * F]; // 25.6 MB fp16 features
__device__ float  g_agg[(long)N_NODES_MAX * F];    // 51.2 MB fp32 aggregate
__device__ uint4  g_Wpack[2048];                   // packed B frags, 32 KB
__device__ int    g_deg[N_NODES_MAX];
__device__ int    g_row_start[N_NODES_MAX + 1];
__device__ int    g_cursor[N_NODES_MAX];
__device__ int    g_csr_src[E_MAX];

// m16n8k16 fp16 x fp16 -> fp32 (base PTX, sm_80+, no 'a' features)
#define MMA16816(d0,d1,d2,d3, a0,a1,a2,a3, b0,b1, c0,c1,c2,c3)                 \
    asm volatile(                                                              \
        "mma.sync.aligned.m16n8k16.row.col.f32.f16.f16.f32 "                   \
        "{%0,%1,%2,%3}, {%4,%5,%6,%7}, {%8,%9}, {%10,%11,%12,%13};"            \
        : "=f"(d0), "=f"(d1), "=f"(d2), "=f"(d3)                               \
        : "r"(a0), "r"(a1), "r"(a2), "r"(a3), "r"(b0), "r"(b1),                \
          "f"(c0), "f"(c1), "f"(c2), "f"(c3))

// ---------------------------------------------------------------------------
// 0a. convert feat fp32 -> fp16
// ---------------------------------------------------------------------------
__global__ void convert_kernel(const float* __restrict__ feat, long total) {
    long i = (long)blockIdx.x * blockDim.x + threadIdx.x;
    long n4 = total / 4;
    for (; i < n4; i += (long)gridDim.x * blockDim.x) {
        float4 v = reinterpret_cast<const float4*>(feat)[i];
        __half2 h0 = __floats2half2_rn(v.x, v.y);
        __half2 h1 = __floats2half2_rn(v.z, v.w);
        uint2 packed;
        packed.x = *reinterpret_cast<unsigned*>(&h0);
        packed.y = *reinterpret_cast<unsigned*>(&h1);
        reinterpret_cast<uint2*>(g_feat_h)[i] = packed;
    }
}

// ---------------------------------------------------------------------------
// 0b. pack B fragments in MMA consumption order (validated R10/R12 layout).
// ---------------------------------------------------------------------------
__global__ void prep_w_kernel(const float* __restrict__ W) {
    int idx = blockIdx.x * blockDim.x + threadIdx.x;  // 0..2047
    if (idx >= 2048) return;
    int g   = idx & 7;
    int tig = (idx >> 3) & 3;
    int ktp = (idx >> 5) & 3;
    int nt  = idx >> 7;
    int ncol = nt * 8 + g;

    auto pack = [&](int k) -> uint32_t {
        __half2 h = __floats2half2_rn(W[k * F + ncol], W[(k + 1) * F + ncol]);
        return *reinterpret_cast<uint32_t*>(&h);
    };
    int k0 = (2 * ktp) * 16 + tig * 2;
    int k1 = (2 * ktp + 1) * 16 + tig * 2;
    uint4 bb;
    bb.x = pack(k0);
    bb.y = pack(k0 + 8);
    bb.z = pack(k1);
    bb.w = pack(k1 + 8);
    g_Wpack[((nt * 4 + ktp) * 4 + tig) * 8 + g] = bb;
}

// ---------------------------------------------------------------------------
// 1. histogram of dst
// ---------------------------------------------------------------------------
__global__ void hist_kernel(const int* __restrict__ dst, int n_edges) {
    int e = blockIdx.x * blockDim.x + threadIdx.x;
    if (e < n_edges) atomicAdd(&g_deg[dst[e]], 1);
}

// ---------------------------------------------------------------------------
// 2. single-BLOCK exclusive scan: g_deg -> g_row_start. grid=1, 1024 thr.
// Each thread owns SCHUNK=100 contiguous elements (100%4==0 -> int4 aligned).
// Serial chunk sum -> two-level shuffle scan -> serial prefix write-back.
// ---------------------------------------------------------------------------
__global__ void __launch_bounds__(1024) scan_kernel(int n_nodes) {
    __shared__ int swarp[32];
    __shared__ int s_total;
    int t = threadIdx.x, lane = t & 31, wid = t >> 5;
    int base = t * SCHUNK;
    int lim = (base < n_nodes) ? min(SCHUNK, n_nodes - base) : 0;

    int tsum = 0;
    {
        int i = 0;
        for (; i + 3 < lim; i += 4) {
            int4 v = *reinterpret_cast<const int4*>(g_deg + base + i);
            tsum += v.x + v.y + v.z + v.w;
        }
        for (; i < lim; i++) tsum += g_deg[base + i];
    }

    // warp inclusive scan of thread sums
    int incl = tsum;
#pragma unroll
    for (int off = 1; off < 32; off <<= 1) {
        int ngh = __shfl_up_sync(0xffffffffu, incl, off);
        if (lane >= off) incl += ngh;
    }
    if (lane == 31) swarp[wid] = incl;
    __syncthreads();

    if (wid == 0) {
        int wv = swarp[lane];
        int wincl = wv;
#pragma unroll
        for (int off = 1; off < 32; off <<= 1) {
            int ngh = __shfl_up_sync(0xffffffffu, wincl, off);
            if (lane >= off) wincl += ngh;
        }
        swarp[lane] = wincl - wv;           // exclusive warp offset
        if (lane == 31) s_total = wincl;
    }
    __syncthreads();

    int run = swarp[wid] + incl - tsum;     // thread's exclusive offset
    {
        int i = 0;
        for (; i + 3 < lim; i += 4) {
            int4 v = *reinterpret_cast<const int4*>(g_deg + base + i);
            int4 o;
            o.x = run;
            o.y = run + v.x;
            o.z = o.y + v.y;
            o.w = o.z + v.z;
            *reinterpret_cast<int4*>(g_row_start + base + i) = o;
            run = o.w + v.w;
        }
        for (; i < lim; i++) { g_row_start[base + i] = run; run += g_deg[base + i]; }
    }
    if (t == 1023) g_row_start[n_nodes] = s_total;
}

// ---------------------------------------------------------------------------
// 3. fill CSR
// ---------------------------------------------------------------------------
__global__ void fill_kernel(const int* __restrict__ src,
                            const int* __restrict__ dst, int n_edges) {
    int e = blockIdx.x * blockDim.x + threadIdx.x;
    if (e >= n_edges) return;
    int d = dst[e];
    int pos = atomicAdd(&g_cursor[d], 1);
    g_csr_src[g_row_start[d] + pos] = src[e];
}

// ---------------------------------------------------------------------------
// 4. gather: one warp per node, 2 edges per iteration via half-warps.
// Lanes 0-15 process even edges, 16-31 odd edges; each lane loads one uint4
// (8 halves = 16B -> LDG.128, 256B coalesced per half-warp). Halves combined
// with shfl_down(16) at node end. Halves shfl+LDG count vs R13.
// ---------------------------------------------------------------------------
__global__ void __launch_bounds__(256) gather_kernel(int n_nodes) {
    int node = blockIdx.x * (blockDim.x >> 5) + (threadIdx.x >> 5);
    if (node >= n_nodes) return;
    int lane = threadIdx.x & 31;
    int half = lane >> 4;     // 0: even edges, 1: odd edges
    int fl   = lane & 15;     // feature slot (8 halves each)

    int beg = g_row_start[node];
    int end = g_row_start[node + 1];

    const uint4* fh4 = reinterpret_cast<const uint4*>(g_feat_h);  // 16 uint4/row

    float acc[8];
#pragma unroll
    for (int f = 0; f < 8; f++) acc[f] = 0.f;

    for (int i = beg; i < end; i += 32) {
        int s_reg = (i + lane < end) ? g_csr_src[i + lane] : 0;
        int cnt = min(32, end - i);
#pragma unroll 4
        for (int j = 0; j < cnt; j += 2) {
            int jj = j + half;
            int s = __shfl_sync(0xffffffffu, s_reg, jj & 31);
            if (jj < cnt) {
                uint4 raw = __ldg(fh4 + (long)s * 16 + fl);
                __half2 h0 = *reinterpret_cast<__half2*>(&raw.x);
                __half2 h1 = *reinterpret_cast<__half2*>(&raw.y);
                __half2 h2 = *reinterpret_cast<__half2*>(&raw.z);
                __half2 h3 = *reinterpret_cast<__half2*>(&raw.w);
                float2 f0 = __half22float2(h0);
                float2 f1 = __half22float2(h1);
                float2 f2 = __half22float2(h2);
                float2 f3 = __half22float2(h3);
                acc[0] += f0.x; acc[1] += f0.y;
                acc[2] += f1.x; acc[3] += f1.y;
                acc[4] += f2.x; acc[5] += f2.y;
                acc[6] += f3.x; acc[7] += f3.y;
            }
        }
    }

    // combine odd-edge partials into lanes 0-15
#pragma unroll
    for (int f = 0; f < 8; f++)
        acc[f] += __shfl_down_sync(0xffffffffu, acc[f], 16);

    if (half == 0) {
        float4* ap = reinterpret_cast<float4*>(g_agg + (long)node * F + fl * 8);
        ap[0] = make_float4(acc[0], acc[1], acc[2], acc[3]);
        ap[1] = make_float4(acc[4], acc[5], acc[6], acc[7]);
    }
}

// ---------------------------------------------------------------------------
// 5. HMMA GEMM + norm + bias (unchanged from R12/R13).
// ---------------------------------------------------------------------------
#define PADH 136
__global__ void __launch_bounds__(256) mma_gemm_kernel(
        const float* __restrict__ bias,
        float* __restrict__ out, int n_nodes) {
    __shared__ __half sA[128 * PADH];   // ~34.8 KB

    int t = threadIdx.x;
    int warp = t >> 5;
    int lane = t & 31;
    int g   = lane >> 2;       // groupID 0..7
    int tig = lane & 3;        // thread-in-group 0..3
    int rb = blockIdx.x * 128;

    // ---- stage agg tile as fp16 ----
    {
        for (int i = 0; i < 32; i++) {
            int idx = t + i * 256;          // half2 index, 64 per row
            int row = idx >> 6;
            int c2 = idx & 63;
            __half2 h;
            if (rb + row < n_nodes) {
                float2 v = *reinterpret_cast<const float2*>(
                    g_agg + (long)(rb + row) * F + c2 * 2);
                h = __floats2half2_rn(v.x, v.y);
            } else {
                h = __floats2half2_rn(0.f, 0.f);
            }
            *reinterpret_cast<__half2*>(&sA[row * PADH + c2 * 2]) = h;
        }
    }
    __syncthreads();

    int mrow = warp * 16;

    // ---- hoist all A fragments: 8 k-tiles x 4 regs ----
    uint32_t a[8][4];
#pragma unroll
    for (int kt = 0; kt < 8; kt++) {
        int k0 = kt * 16 + tig * 2;
        a[kt][0] = *reinterpret_cast<const uint32_t*>(&sA[(mrow + g)     * PADH + k0]);
        a[kt][1] = *reinterpret_cast<const uint32_t*>(&sA[(mrow + g + 8) * PADH + k0]);
        a[kt][2] = *reinterpret_cast<const uint32_t*>(&sA[(mrow + g)     * PADH + k0 + 8]);
        a[kt][3] = *reinterpret_cast<const uint32_t*>(&sA[(mrow + g + 8) * PADH + k0 + 8]);
    }

    int row0 = rb + mrow + g;
    int row1 = row0 + 8;
    float nrm0 = (row0 < n_nodes) ? rsqrtf(fmaxf((float)g_deg[row0], 1.0f)) : 0.f;
    float nrm1 = (row1 < n_nodes) ? rsqrtf(fmaxf((float)g_deg[row1], 1.0f)) : 0.f;

#pragma unroll
    for (int nt = 0; nt < 16; nt++) {
        int nb = nt * 8;
        float c0 = 0.f, c1 = 0.f, c2 = 0.f, c3 = 0.f;
#pragma unroll
        for (int ktp = 0; ktp < 4; ktp++) {
            uint4 bb = __ldg(&g_Wpack[((nt * 4 + ktp) * 4 + tig) * 8 + g]);
            int kt0 = 2 * ktp, kt1 = kt0 + 1;
            MMA16816(c0, c1, c2, c3,
                     a[kt0][0], a[kt0][1], a[kt0][2], a[kt0][3],
                     bb.x, bb.y, c0, c1, c2, c3);
            MMA16816(c0, c1, c2, c3,
                     a[kt1][0], a[kt1][1], a[kt1][2], a[kt1][3],
                     bb.z, bb.w, c0, c1, c2, c3);
        }
        float2 bv = __ldg(reinterpret_cast<const float2*>(bias + nb + tig * 2));
        if (row0 < n_nodes) {
            float2 o0;
            o0.x = c0 * nrm0 + bv.x;
            o0.y = c1 * nrm0 + bv.y;
            *reinterpret_cast<float2*>(out + (long)row0 * F + nb + tig * 2) = o0;
        }
        if (row1 < n_nodes) {
            float2 o1;
            o1.x = c2 * nrm1 + bv.x;
            o1.y = c3 * nrm1 + bv.y;
            *reinterpret_cast<float2*>(out + (long)row1 * F + nb + tig * 2) = o1;
        }
    }
}

// ---------------------------------------------------------------------------
extern "C" void kernel_launch(void* const* d_in, const int* in_sizes, int n_in,
                              void* d_out, int out_size) {
    const float* feat   = (const float*)d_in[0];
    const int*   src    = (const int*)d_in[1];
    const int*   dst    = (const int*)d_in[2];
    const float* weight = (const float*)d_in[3];
    const float* bias   = (const float*)d_in[4];
    float* out = (float*)d_out;

    int n_nodes = in_sizes[0] / F;
    int n_edges = in_sizes[1];

    int eb = (n_edges + 255) / 256;

    void* deg_ptr = nullptr;
    void* cur_ptr = nullptr;
    cudaGetSymbolAddress(&deg_ptr, g_deg);
    cudaGetSymbolAddress(&cur_ptr, g_cursor);
    cudaMemsetAsync(deg_ptr, 0, (size_t)n_nodes * sizeof(int));
    cudaMemsetAsync(cur_ptr, 0, (size_t)n_nodes * sizeof(int));

    convert_kernel<<<1024, 256>>>(feat, (long)n_nodes * F);
    prep_w_kernel<<<8, 256>>>(weight);
    hist_kernel<<<eb, 256>>>(dst, n_edges);
    scan_kernel<<<1, 1024>>>(n_nodes);
    fill_kernel<<<eb, 256>>>(src, dst, n_edges);

    int warps_per_block = 256 / 32;
    int gather_blocks = (n_nodes + warps_per_block - 1) / warps_per_block;
    gather_kernel<<<gather_blocks, 256>>>(n_nodes);

    int gemm_blocks = (n_nodes + 127) / 128;
    mma_gemm_kernel<<<gemm_blocks, 256>>>(bias, out, n_nodes);
}

// round 15
// speedup vs baseline: 1.2143x; 1.2143x over previous
#include <cuda_runtime.h>
#include <cuda_fp16.h>
#include <cuda_bf16.h>
#include <cstdint>

#define N_NODES_MAX 100000
#define E_MAX       1600000
#define F           128
#define SC          4096          // elements per scan block (1024 thr x 4)
#define SCAN_BMAX   32

// ===========================================================================
// Scratch (allocation-free contract: __device__ globals)
// ===========================================================================
__device__ __half g_feat_h[(long)N_NODES_MAX * F]; // 25.6 MB fp16 features
__device__ float  g_agg[(long)N_NODES_MAX * F];    // 51.2 MB fp32 aggregate
__device__ uint4  g_Wpack[2048];                   // packed B frags, 32 KB
__device__ int    g_deg[N_NODES_MAX];
__device__ int    g_row_start[N_NODES_MAX + 1];
__device__ int    g_cursor[N_NODES_MAX];
__device__ int    g_csr_src[E_MAX];
__device__ int    g_aggr[SCAN_BMAX];               // per-block scan aggregates

// m16n8k16 fp16 x fp16 -> fp32 (base PTX, sm_80+, no 'a' features)
#define MMA16816(d0,d1,d2,d3, a0,a1,a2,a3, b0,b1, c0,c1,c2,c3)                 \
    asm volatile(                                                              \
        "mma.sync.aligned.m16n8k16.row.col.f32.f16.f16.f32 "                   \
        "{%0,%1,%2,%3}, {%4,%5,%6,%7}, {%8,%9}, {%10,%11,%12,%13};"            \
        : "=f"(d0), "=f"(d1), "=f"(d2), "=f"(d3)                               \
        : "r"(a0), "r"(a1), "r"(a2), "r"(a3), "r"(b0), "r"(b1),                \
          "f"(c0), "f"(c1), "f"(c2), "f"(c3))

// ---------------------------------------------------------------------------
// 0a. convert feat fp32 -> fp16
// ---------------------------------------------------------------------------
__global__ void convert_kernel(const float* __restrict__ feat, long total) {
    long i = (long)blockIdx.x * blockDim.x + threadIdx.x;
    long n4 = total / 4;
    for (; i < n4; i += (long)gridDim.x * blockDim.x) {
        float4 v = reinterpret_cast<const float4*>(feat)[i];
        __half2 h0 = __floats2half2_rn(v.x, v.y);
        __half2 h1 = __floats2half2_rn(v.z, v.w);
        uint2 packed;
        packed.x = *reinterpret_cast<unsigned*>(&h0);
        packed.y = *reinterpret_cast<unsigned*>(&h1);
        reinterpret_cast<uint2*>(g_feat_h)[i] = packed;
    }
}

// ---------------------------------------------------------------------------
// 0b. pack B fragments in MMA consumption order (validated R10/R12 layout).
// ---------------------------------------------------------------------------
__global__ void prep_w_kernel(const float* __restrict__ W) {
    int idx = blockIdx.x * blockDim.x + threadIdx.x;  // 0..2047
    if (idx >= 2048) return;
    int g   = idx & 7;
    int tig = (idx >> 3) & 3;
    int ktp = (idx >> 5) & 3;
    int nt  = idx >> 7;
    int ncol = nt * 8 + g;

    auto pack = [&](int k) -> uint32_t {
        __half2 h = __floats2half2_rn(W[k * F + ncol], W[(k + 1) * F + ncol]);
        return *reinterpret_cast<uint32_t*>(&h);
    };
    int k0 = (2 * ktp) * 16 + tig * 2;
    int k1 = (2 * ktp + 1) * 16 + tig * 2;
    uint4 bb;
    bb.x = pack(k0);
    bb.y = pack(k0 + 8);
    bb.z = pack(k1);
    bb.w = pack(k1 + 8);
    g_Wpack[((nt * 4 + ktp) * 4 + tig) * 8 + g] = bb;
}

// ---------------------------------------------------------------------------
// 1. histogram of dst
// ---------------------------------------------------------------------------
__global__ void hist_kernel(const int* __restrict__ dst, int n_edges) {
    int e = blockIdx.x * blockDim.x + threadIdx.x;
    if (e < n_edges) atomicAdd(&g_deg[dst[e]], 1);
}

// ---------------------------------------------------------------------------
// 2. single-pass exclusive scan with PARALLEL lookback.
// Coalesced int4 loads (base = b*SC + t*4). Each block publishes its
// aggregate immediately; warp 0's lanes poll all predecessors CONCURRENTLY
// (one lane per predecessor, b <= 25 < 32), then shuffle-reduce.
// All 25 blocks resident (25 <= 148 SMs) -> forward progress guaranteed.
// ---------------------------------------------------------------------------
__global__ void __launch_bounds__(1024) scan_chain_kernel(int n_nodes, int n_blocks) {
    __shared__ int swarp[32];
    __shared__ int s_total;
    __shared__ int s_prev;
    int b = blockIdx.x, t = threadIdx.x;
    int lane = t & 31, wid = t >> 5;
    int base = b * SC + t * 4;

    int4 v = make_int4(0, 0, 0, 0);
    if (base + 3 < n_nodes) {
        v = *reinterpret_cast<const int4*>(g_deg + base);
    } else {
        if (base + 0 < n_nodes) v.x = g_deg[base + 0];
        if (base + 1 < n_nodes) v.y = g_deg[base + 1];
        if (base + 2 < n_nodes) v.z = g_deg[base + 2];
        if (base + 3 < n_nodes) v.w = g_deg[base + 3];
    }
    int tsum = v.x + v.y + v.z + v.w;

    // warp inclusive scan of thread sums
    int incl = tsum;
#pragma unroll
    for (int off = 1; off < 32; off <<= 1) {
        int ngh = __shfl_up_sync(0xffffffffu, incl, off);
        if (lane >= off) incl += ngh;
    }
    if (lane == 31) swarp[wid] = incl;
    __syncthreads();

    // warp 0: scan warp totals, publish aggregate, parallel lookback
    if (wid == 0) {
        int wv = swarp[lane];
        int wincl = wv;
#pragma unroll
        for (int off = 1; off < 32; off <<= 1) {
            int ngh = __shfl_up_sync(0xffffffffu, wincl, off);
            if (lane >= off) wincl += ngh;
        }
        swarp[lane] = wincl - wv;           // exclusive warp offset
        int total = __shfl_sync(0xffffffffu, wincl, 31);
        if (lane == 0) {
            s_total = total;
            atomicExch(&g_aggr[b], total);  // publish immediately
        }

        // each lane polls ONE predecessor concurrently
        int contrib = 0;
        if (lane < b) {
            int a;
            while ((a = atomicAdd(&g_aggr[lane], 0)) < 0) { }
            contrib = a;
        }
#pragma unroll
        for (int off = 16; off > 0; off >>= 1)
            contrib += __shfl_down_sync(0xffffffffu, contrib, off);
        if (lane == 0) s_prev = contrib;
    }
    __syncthreads();

    int e0 = s_prev + swarp[wid] + incl - tsum;
    if (base + 0 < n_nodes) g_row_start[base + 0] = e0;
    if (base + 1 < n_nodes) g_row_start[base + 1] = e0 + v.x;
    if (base + 2 < n_nodes) g_row_start[base + 2] = e0 + v.x + v.y;
    if (base + 3 < n_nodes) g_row_start[base + 3] = e0 + v.x + v.y + v.z;
    if (b == n_blocks - 1 && t == 1023) g_row_start[n_nodes] = s_prev + s_total;
}

// ---------------------------------------------------------------------------
// 3. fill CSR
// ---------------------------------------------------------------------------
__global__ void fill_kernel(const int* __restrict__ src,
                            const int* __restrict__ dst, int n_edges) {
    int e = blockIdx.x * blockDim.x + threadIdx.x;
    if (e >= n_edges) return;
    int d = dst[e];
    int pos = atomicAdd(&g_cursor[d], 1);
    g_csr_src[g_row_start[d] + pos] = src[e];
}

// ---------------------------------------------------------------------------
// 4. gather (fp16 reads, fp32 accumulate): one warp per node (R13 version)
// ---------------------------------------------------------------------------
__global__ void __launch_bounds__(256) gather_kernel(int n_nodes) {
    int node = blockIdx.x * (blockDim.x >> 5) + (threadIdx.x >> 5);
    if (node >= n_nodes) return;
    int lane = threadIdx.x & 31;

    int beg = g_row_start[node];
    int end = g_row_start[node + 1];

    const uint2* fh = reinterpret_cast<const uint2*>(g_feat_h);

    float4 acc = make_float4(0.f, 0.f, 0.f, 0.f);
    for (int i = beg; i < end; i += 32) {
        int s_reg = (i + lane < end) ? g_csr_src[i + lane] : 0;
        int cnt = min(32, end - i);
#pragma unroll 8
        for (int j = 0; j < cnt; j++) {
            int s = __shfl_sync(0xffffffffu, s_reg, j);
            uint2 raw = __ldg(fh + (long)s * 32 + lane);
            __half2 h0 = *reinterpret_cast<__half2*>(&raw.x);
            __half2 h1 = *reinterpret_cast<__half2*>(&raw.y);
            float2 f0 = __half22float2(h0);
            float2 f1 = __half22float2(h1);
            acc.x += f0.x; acc.y += f0.y;
            acc.z += f1.x; acc.w += f1.y;
        }
    }
    *reinterpret_cast<float4*>(g_agg + (long)node * F + lane * 4) = acc;
}

// ---------------------------------------------------------------------------
// 5. HMMA GEMM + norm + bias (unchanged from R12/R13).
// ---------------------------------------------------------------------------
#define PADH 136
__global__ void __launch_bounds__(256) mma_gemm_kernel(
        const float* __restrict__ bias,
        float* __restrict__ out, int n_nodes) {
    __shared__ __half sA[128 * PADH];   // ~34.8 KB

    int t = threadIdx.x;
    int warp = t >> 5;
    int lane = t & 31;
    int g   = lane >> 2;       // groupID 0..7
    int tig = lane & 3;        // thread-in-group 0..3
    int rb = blockIdx.x * 128;

    // ---- stage agg tile as fp16 ----
    {
        for (int i = 0; i < 32; i++) {
            int idx = t + i * 256;          // half2 index, 64 per row
            int row = idx >> 6;
            int c2 = idx & 63;
            __half2 h;
            if (rb + row < n_nodes) {
                float2 v = *reinterpret_cast<const float2*>(
                    g_agg + (long)(rb + row) * F + c2 * 2);
                h = __floats2half2_rn(v.x, v.y);
            } else {
                h = __floats2half2_rn(0.f, 0.f);
            }
            *reinterpret_cast<__half2*>(&sA[row * PADH + c2 * 2]) = h;
        }
    }
    __syncthreads();

    int mrow = warp * 16;

    // ---- hoist all A fragments: 8 k-tiles x 4 regs ----
    uint32_t a[8][4];
#pragma unroll
    for (int kt = 0; kt < 8; kt++) {
        int k0 = kt * 16 + tig * 2;
        a[kt][0] = *reinterpret_cast<const uint32_t*>(&sA[(mrow + g)     * PADH + k0]);
        a[kt][1] = *reinterpret_cast<const uint32_t*>(&sA[(mrow + g + 8) * PADH + k0]);
        a[kt][2] = *reinterpret_cast<const uint32_t*>(&sA[(mrow + g)     * PADH + k0 + 8]);
        a[kt][3] = *reinterpret_cast<const uint32_t*>(&sA[(mrow + g + 8) * PADH + k0 + 8]);
    }

    int row0 = rb + mrow + g;
    int row1 = row0 + 8;
    float nrm0 = (row0 < n_nodes) ? rsqrtf(fmaxf((float)g_deg[row0], 1.0f)) : 0.f;
    float nrm1 = (row1 < n_nodes) ? rsqrtf(fmaxf((float)g_deg[row1], 1.0f)) : 0.f;

#pragma unroll
    for (int nt = 0; nt < 16; nt++) {
        int nb = nt * 8;
        float c0 = 0.f, c1 = 0.f, c2 = 0.f, c3 = 0.f;
#pragma unroll
        for (int ktp = 0; ktp < 4; ktp++) {
            uint4 bb = __ldg(&g_Wpack[((nt * 4 + ktp) * 4 + tig) * 8 + g]);
            int kt0 = 2 * ktp, kt1 = kt0 + 1;
            MMA16816(c0, c1, c2, c3,
                     a[kt0][0], a[kt0][1], a[kt0][2], a[kt0][3],
                     bb.x, bb.y, c0, c1, c2, c3);
            MMA16816(c0, c1, c2, c3,
                     a[kt1][0], a[kt1][1], a[kt1][2], a[kt1][3],
                     bb.z, bb.w, c0, c1, c2, c3);
        }
        float2 bv = __ldg(reinterpret_cast<const float2*>(bias + nb + tig * 2));
        if (row0 < n_nodes) {
            float2 o0;
            o0.x = c0 * nrm0 + bv.x;
            o0.y = c1 * nrm0 + bv.y;
            *reinterpret_cast<float2*>(out + (long)row0 * F + nb + tig * 2) = o0;
        }
        if (row1 < n_nodes) {
            float2 o1;
            o1.x = c2 * nrm1 + bv.x;
            o1.y = c3 * nrm1 + bv.y;
            *reinterpret_cast<float2*>(out + (long)row1 * F + nb + tig * 2) = o1;
        }
    }
}

// ---------------------------------------------------------------------------
extern "C" void kernel_launch(void* const* d_in, const int* in_sizes, int n_in,
                              void* d_out, int out_size) {
    const float* feat   = (const float*)d_in[0];
    const int*   src    = (const int*)d_in[1];
    const int*   dst    = (const int*)d_in[2];
    const float* weight = (const float*)d_in[3];
    const float* bias   = (const float*)d_in[4];
    float* out = (float*)d_out;

    int n_nodes = in_sizes[0] / F;
    int n_edges = in_sizes[1];

    int eb = (n_edges + 255) / 256;
    int scan_blocks = (n_nodes + SC - 1) / SC;

    void* deg_ptr = nullptr;
    void* cur_ptr = nullptr;
    void* aggr_ptr = nullptr;
    cudaGetSymbolAddress(&deg_ptr, g_deg);
    cudaGetSymbolAddress(&cur_ptr, g_cursor);
    cudaGetSymbolAddress(&aggr_ptr, g_aggr);
    cudaMemsetAsync(deg_ptr, 0, (size_t)n_nodes * sizeof(int));
    cudaMemsetAsync(cur_ptr, 0, (size_t)n_nodes * sizeof(int));
    cudaMemsetAsync(aggr_ptr, 0xFF, SCAN_BMAX * sizeof(int));   // -1 sentinels

    convert_kernel<<<1024, 256>>>(feat, (long)n_nodes * F);
    prep_w_kernel<<<8, 256>>>(weight);
    hist_kernel<<<eb, 256>>>(dst, n_edges);
    scan_chain_kernel<<<scan_blocks, 1024>>>(n_nodes, scan_blocks);
    fill_kernel<<<eb, 256>>>(src, dst, n_edges);

    int warps_per_block = 256 / 32;
    int gather_blocks = (n_nodes + warps_per_block - 1) / warps_per_block;
    gather_kernel<<<gather_blocks, 256>>>(n_nodes);

    int gemm_blocks = (n_nodes + 127) / 128;
    mma_gemm_kernel<<<gemm_blocks, 256>>>(bias, out, n_nodes);
}